// round 4
// baseline (speedup 1.0000x reference)
#include <cuda_runtime.h>
#include <cuda_bf16.h>

// HighDimAELoss: associative-embedding push/pull loss.
// tags:   [B=16, D=17, R=512, R=512] float32
// joints: [B=16, M=30, J=17, 2] int32  (flat heatmap idx, visibility)
// out:    [2*B] float32  -> out[0:16]=push, out[16:32]=pull
//
// Single fused kernel: 480 CTAs (one per person). Each CTA gathers its
// person's valid tag vectors, computes mean-tag / pull contribution, then
// takes a ticket; the last CTA of each image finalizes push+pull inline
// (threadfence-reduction pattern). Counter is reset by the finisher so the
// kernel is graph-replayable.

#define B_IMG   16
#define M_PPL   30
#define N_JNT   17
#define AE_D    17
#define AE_DP   18          // padded row to avoid smem bank conflicts
#define RESO    512
#define NTHREADS 128

// scratch (device globals - no allocation allowed)
__device__ float g_mean [B_IMG * M_PPL * AE_D];
__device__ float g_pv   [B_IMG * M_PPL];
__device__ float g_pullc[B_IMG * M_PPL];   // pull_p * person_valid
__device__ int   g_tick [B_IMG];           // zero-init; finisher resets

__global__ __launch_bounds__(NTHREADS)
void ae_fused_kernel(const float* __restrict__ tags,
                     const int*   __restrict__ joints,
                     float*       __restrict__ out) {
    const int bm  = blockIdx.x;          // b * M_PPL + m
    const int b   = bm / M_PPL;
    const int tid = threadIdx.x;

    __shared__ float tS[N_JNT * AE_DP];  // gathered tag vectors [j][d], padded
    __shared__ float validS[N_JNT];
    __shared__ int   xS[N_JNT];
    __shared__ int   yS[N_JNT];
    __shared__ float sqS[N_JNT];
    __shared__ float s_cnt;
    __shared__ int   s_ticket;

    const float* tagb = tags + (size_t)b * AE_D * RESO * RESO;
    const int*   jb   = joints + (size_t)bm * N_JNT * 2;

    // ---- decode joints ----
    if (tid < N_JNT) {
        int idx = jb[2 * tid];
        int vis = jb[2 * tid + 1];
        int off = idx % (RESO * RESO);
        if (off < 0) off += RESO * RESO;
        xS[tid] = off % RESO;
        yS[tid] = off / RESO;
        validS[tid] = (vis > 0) ? 1.0f : 0.0f;
    }
    __syncthreads();

    // ---- gather (valid joints only; invalid tags are dead in the math) ----
    for (int e = tid; e < N_JNT * AE_D; e += NTHREADS) {
        int d = e % AE_D;
        int j = e / AE_D;
        float v = 0.0f;
        if (validS[j] > 0.0f)
            v = __ldg(&tagb[(size_t)d * (RESO * RESO) + (size_t)xS[j] * RESO + yS[j]]);
        tS[j * AE_DP + d] = v;
    }
    __syncthreads();

    // ---- per-joint pairwise-sq sum: 2*D*sum(t^2) - 2*(sum t)^2 ----
    if (tid < N_JNT) {
        float s1 = 0.f, s2 = 0.f;
        #pragma unroll
        for (int d = 0; d < AE_D; d++) {
            float v = tS[tid * AE_DP + d];
            s1 += v; s2 += v * v;
        }
        sqS[tid] = 2.0f * (float)AE_D * s2 - 2.0f * s1 * s1;
        if (tid == 0) {
            float c = 0.f;
            #pragma unroll
            for (int j = 0; j < N_JNT; j++) c += validS[j];
            s_cnt = c;
        }
    }
    __syncthreads();

    const float cnt  = s_cnt;
    const float safe = fmaxf(cnt, 1.0f);
    const float pv   = (cnt > 0.f) ? 1.0f : 0.0f;

    // ---- mean tag per dim ----
    if (tid < AE_D) {
        float acc = 0.f;
        #pragma unroll
        for (int j = 0; j < N_JNT; j++)
            acc += tS[j * AE_DP + tid] * validS[j];
        g_mean[bm * AE_D + tid] = acc / safe;
    }

    // ---- pull contribution ----
    if (tid == 0) {
        float pp = 0.f;
        #pragma unroll
        for (int j = 0; j < N_JNT; j++) pp += sqS[j] * validS[j];
        pp /= ((float)(AE_D * AE_D) * safe);
        g_pullc[bm] = pp * pv;
        g_pv[bm]    = pv;
    }

    // ---- publish + take ticket ----
    __threadfence();
    __syncthreads();
    if (tid == 0) s_ticket = atomicAdd(&g_tick[b], 1);
    __syncthreads();
    if (s_ticket != M_PPL - 1) return;

    // =======================================================================
    // Finisher CTA for image b: all 30 persons' results are globally visible
    // (each producer fenced before its atomicAdd).
    // =======================================================================
    __threadfence();

    __shared__ float meanS[M_PPL * AE_D];
    __shared__ float pvS[M_PPL];
    __shared__ float red[NTHREADS];
    __shared__ float s_pull, s_ntags;

    for (int i = tid; i < M_PPL * AE_D; i += NTHREADS)
        meanS[i] = __ldcg(&g_mean[b * M_PPL * AE_D + i]);
    if (tid < M_PPL) pvS[tid] = __ldcg(&g_pv[b * M_PPL + tid]);
    if (tid == 0) {
        float pull = 0.f, ntags = 0.f;
        for (int m = 0; m < M_PPL; m++) {
            pull  += __ldcg(&g_pullc[b * M_PPL + m]);
            ntags += __ldcg(&g_pv[b * M_PPL + m]);
        }
        s_pull  = pull / fmaxf(ntags, 1.0f);
        s_ntags = ntags;
        g_tick[b] = 0;                    // reset for next graph replay
    }
    __syncthreads();

    // push: pairwise exp(-diff^2) between mean tags (diagonal included)
    float local = 0.f;
    for (int p = tid; p < M_PPL * M_PPL; p += NTHREADS) {
        int m = p / M_PPL;
        int n = p % M_PPL;
        float w = pvS[m] * pvS[n];
        if (w > 0.f) {
            float s = 0.f;
            #pragma unroll
            for (int d = 0; d < AE_D; d++) {
                float dd = meanS[m * AE_D + d] - meanS[n * AE_D + d];
                s += __expf(-dd * dd);
            }
            local += s * (1.0f / (float)AE_D);
        }
    }
    red[tid] = local;
    __syncthreads();
    for (int stride = NTHREADS / 2; stride > 0; stride >>= 1) {
        if (tid < stride) red[tid] += red[tid + stride];
        __syncthreads();
    }

    if (tid == 0) {
        float nt    = s_ntags;
        float denom = fmaxf(nt, 1.0f);
        out[b]         = (nt >= 2.0f) ? red[0] / (denom * denom) : 0.0f; // push
        out[B_IMG + b] = s_pull;                                         // pull
    }
}

extern "C" void kernel_launch(void* const* d_in, const int* in_sizes, int n_in,
                              void* d_out, int out_size) {
    const float* tags   = (const float*)d_in[0];
    const int*   joints = (const int*)d_in[1];
    float*       out    = (float*)d_out;
    ae_fused_kernel<<<B_IMG * M_PPL, NTHREADS>>>(tags, joints, out);
}

// round 8
// speedup vs baseline: 1.0025x; 1.0025x over previous
#include <cuda_runtime.h>
#include <cuda_bf16.h>
#include <cstdint>

// HighDimAELoss: associative-embedding push/pull loss.
// tags:   [B=16, D=17, R=512, R=512] float32
// joints: [B=16, M=30, J=17, 2] int32  (flat heatmap idx, visibility)
// out:    [2*B] float32  -> out[0:16]=push, out[16:32]=pull
//
// Single launch: 16 clusters x 8 CTAs (one cluster per image), 128 thr/CTA.
// Each CTA gathers/reduces <=4 persons into its SMEM; cluster barrier; the
// rank-0 CTA pulls peer results via DSMEM (mapa + ld.shared::cluster) and
// finalizes push+pull. No global scratch, no gmem fences, no atomics.

#define B_IMG   16
#define M_PPL   30
#define N_JNT   17
#define AE_D    17
#define AE_DP   18
#define RESO    512
#define CLU     8
#define PPC     4            // persons per CTA (last CTA gets 2)
#define NTHREADS 128

__device__ __forceinline__ float dsmem_ld_f32(const float* p, uint32_t rank) {
    uint32_t la = (uint32_t)__cvta_generic_to_shared((void*)p);
    uint32_t ra;
    asm volatile("mapa.shared::cluster.u32 %0, %1, %2;" : "=r"(ra) : "r"(la), "r"(rank));
    float v;
    asm volatile("ld.shared::cluster.f32 %0, [%1];" : "=f"(v) : "r"(ra));
    return v;
}

__global__ __launch_bounds__(NTHREADS) __cluster_dims__(CLU, 1, 1)
void ae_cluster_kernel(const float* __restrict__ tags,
                       const int*   __restrict__ joints,
                       float*       __restrict__ out) {
    const int b    = blockIdx.x / CLU;
    const int rank = blockIdx.x % CLU;
    const int tid  = threadIdx.x;
    const int p0   = rank * PPC;                      // first person of this CTA
    const int np   = (p0 + PPC <= M_PPL) ? PPC : (M_PPL - p0);   // 4 or 2

    // ---- per-CTA work arrays ----
    __shared__ float tS[PPC * N_JNT * AE_DP];         // gathered tags [p][j][d]
    __shared__ float validS[PPC * N_JNT];
    __shared__ int   xS[PPC * N_JNT];
    __shared__ int   yS[PPC * N_JNT];
    __shared__ float sqS[PPC * N_JNT];
    __shared__ float cntS[PPC];
    // ---- published results (identical layout in every CTA) ----
    __shared__ float res_mean [PPC * AE_D];
    __shared__ float res_pv   [PPC];
    __shared__ float res_pullc[PPC];
    // ---- finisher (rank 0 only uses these) ----
    __shared__ float meanS[M_PPL * AE_D];
    __shared__ float pvS[M_PPL];
    __shared__ float red[NTHREADS];
    __shared__ float s_pull, s_ntags;

    const float* tagb = tags + (size_t)b * AE_D * RESO * RESO;
    const int*   jb   = joints + ((size_t)b * M_PPL + p0) * N_JNT * 2;

    // ---- decode joints for my persons ----
    for (int i = tid; i < np * N_JNT; i += NTHREADS) {
        int idx = jb[2 * i];
        int vis = jb[2 * i + 1];
        int off = idx % (RESO * RESO);
        if (off < 0) off += RESO * RESO;
        xS[i] = off % RESO;
        yS[i] = off / RESO;
        validS[i] = (vis > 0) ? 1.0f : 0.0f;
    }
    __syncthreads();

    // ---- gather (valid joints only; invalid tags multiplied by 0 anyway) ----
    for (int e = tid; e < np * N_JNT * AE_D; e += NTHREADS) {
        int d  = e % AE_D;
        int pj = e / AE_D;                            // p*N_JNT + j
        float v = 0.0f;
        if (validS[pj] > 0.0f)
            v = __ldg(&tagb[(size_t)d * (RESO * RESO) + (size_t)xS[pj] * RESO + yS[pj]]);
        tS[pj * AE_DP + d] = v;
    }
    __syncthreads();

    // ---- per-(p,j) pairwise-sq sum: 2*D*sum(t^2) - 2*(sum t)^2 ----
    for (int i = tid; i < np * N_JNT; i += NTHREADS) {
        float s1 = 0.f, s2 = 0.f;
        #pragma unroll
        for (int d = 0; d < AE_D; d++) {
            float v = tS[i * AE_DP + d];
            s1 += v; s2 += v * v;
        }
        sqS[i] = 2.0f * (float)AE_D * s2 - 2.0f * s1 * s1;
    }
    if (tid < np) {
        float c = 0.f;
        #pragma unroll
        for (int j = 0; j < N_JNT; j++) c += validS[tid * N_JNT + j];
        cntS[tid] = c;
    }
    __syncthreads();

    // ---- mean tag per (p,d) ----
    for (int i = tid; i < np * AE_D; i += NTHREADS) {
        int p = i / AE_D;
        int d = i % AE_D;
        float safe = fmaxf(cntS[p], 1.0f);
        float acc = 0.f;
        #pragma unroll
        for (int j = 0; j < N_JNT; j++)
            acc += tS[(p * N_JNT + j) * AE_DP + d] * validS[p * N_JNT + j];
        res_mean[p * AE_D + d] = acc / safe;
    }
    // ---- pull contribution per person ----
    if (tid < np) {
        float c    = cntS[tid];
        float safe = fmaxf(c, 1.0f);
        float pv   = (c > 0.f) ? 1.0f : 0.0f;
        float pp = 0.f;
        #pragma unroll
        for (int j = 0; j < N_JNT; j++)
            pp += sqS[tid * N_JNT + j] * validS[tid * N_JNT + j];
        pp /= ((float)(AE_D * AE_D) * safe);
        res_pullc[tid] = pp * pv;
        res_pv[tid]    = pv;
    }
    __syncthreads();

    // ---- publish to cluster ----
    asm volatile("barrier.cluster.arrive.aligned;" ::: "memory");
    asm volatile("barrier.cluster.wait.aligned;"   ::: "memory");

    // ---- rank 0 copies all 30 persons' results from peer SMEM ----
    if (rank == 0) {
        for (int i = tid; i < M_PPL * AE_D; i += NTHREADS) {
            int m  = i / AE_D;
            int d  = i % AE_D;
            int rm = m >> 2;                          // owner rank (29>>2 == 7)
            int lp = m - rm * PPC;
            meanS[i] = dsmem_ld_f32(&res_mean[lp * AE_D + d], (uint32_t)rm);
        }
        if (tid < M_PPL) {
            int rm = tid >> 2;
            int lp = tid - rm * PPC;
            pvS[tid] = dsmem_ld_f32(&res_pv[lp], (uint32_t)rm);
            red[tid] = dsmem_ld_f32(&res_pullc[lp], (uint32_t)rm);  // borrow red[] for pullc
        }
        __syncthreads();
        if (tid == 0) {
            float pull = 0.f, ntags = 0.f;
            for (int m = 0; m < M_PPL; m++) { pull += red[m]; ntags += pvS[m]; }
            s_pull  = pull / fmaxf(ntags, 1.0f);
            s_ntags = ntags;
        }
        __syncthreads();
    }

    // ---- release peers (their SMEM no longer needed) ----
    asm volatile("barrier.cluster.arrive.aligned;" ::: "memory");
    asm volatile("barrier.cluster.wait.aligned;"   ::: "memory");
    if (rank != 0) return;

    // ---- push: pairwise exp(-diff^2) between mean tags (diag included) ----
    float local = 0.f;
    for (int p = tid; p < M_PPL * M_PPL; p += NTHREADS) {
        int m = p / M_PPL;
        int n = p % M_PPL;
        float w = pvS[m] * pvS[n];
        if (w > 0.f) {
            float s = 0.f;
            #pragma unroll
            for (int d = 0; d < AE_D; d++) {
                float dd = meanS[m * AE_D + d] - meanS[n * AE_D + d];
                s += __expf(-dd * dd);
            }
            local += s * (1.0f / (float)AE_D);
        }
    }
    red[tid] = local;
    __syncthreads();
    for (int stride = NTHREADS / 2; stride > 0; stride >>= 1) {
        if (tid < stride) red[tid] += red[tid + stride];
        __syncthreads();
    }

    if (tid == 0) {
        float nt    = s_ntags;
        float denom = fmaxf(nt, 1.0f);
        out[b]         = (nt >= 2.0f) ? red[0] / (denom * denom) : 0.0f; // push
        out[B_IMG + b] = s_pull;                                         // pull
    }
}

extern "C" void kernel_launch(void* const* d_in, const int* in_sizes, int n_in,
                              void* d_out, int out_size) {
    const float* tags   = (const float*)d_in[0];
    const int*   joints = (const int*)d_in[1];
    float*       out    = (float*)d_out;
    ae_cluster_kernel<<<B_IMG * CLU, NTHREADS>>>(tags, joints, out);
}